// round 6
// baseline (speedup 1.0000x reference)
#include <cuda_runtime.h>
#include <cstdint>

namespace {
constexpr int Sc = 1024, Dc = 64, BH = 128;
constexpr int TQ = 16, NT = 256;
constexpr int KT = 32;              // rows per K/V stage tile
constexpr int SQ_P = 68;
constexpr int SS_P = 1028;
constexpr int KP = 68, VP = 72;     // per-type pitches (conflict-free frags)
constexpr int BUF = KT * VP;        // 2304 floats per stage buffer
constexpr int SMEM_FLOATS = 16 + TQ * SS_P + TQ * SQ_P + 4 * BUF;  // 26768
constexpr size_t ATTN_OFF = (size_t)BH * Sc * Dc;
}

__device__ __forceinline__ float to_tf32(float x) {
    uint32_t u;
    asm("cvt.rna.tf32.f32 %0, %1;" : "=r"(u) : "f"(x));
    return __uint_as_float(u);
}

__device__ __forceinline__ void mma8(float c[4],
                                     float a0, float a1, float a2, float a3,
                                     float b0, float b1) {
    asm volatile(
        "mma.sync.aligned.m16n8k8.row.col.f32.tf32.tf32.f32 "
        "{%0,%1,%2,%3}, {%4,%5,%6,%7}, {%8,%9}, {%0,%1,%2,%3};\n"
        : "+f"(c[0]), "+f"(c[1]), "+f"(c[2]), "+f"(c[3])
        : "r"(__float_as_uint(a0)), "r"(__float_as_uint(a1)),
          "r"(__float_as_uint(a2)), "r"(__float_as_uint(a3)),
          "r"(__float_as_uint(b0)), "r"(__float_as_uint(b1)));
}

__device__ __forceinline__ uint32_t s2u(const void* p) {
    uint32_t a;
    asm("{ .reg .u64 t; cvta.to.shared.u64 t, %1; cvt.u32.u64 %0, t; }"
        : "=r"(a) : "l"(p));
    return a;
}
__device__ __forceinline__ void mbar_init(uint32_t m, uint32_t cnt) {
    asm volatile("mbarrier.init.shared.b64 [%0], %1;" :: "r"(m), "r"(cnt) : "memory");
}
__device__ __forceinline__ void mbar_arrive(uint32_t m) {
    asm volatile("mbarrier.arrive.shared.b64 _, [%0];" :: "r"(m) : "memory");
}
__device__ __forceinline__ void mbar_wait(uint32_t m, uint32_t parity) {
    asm volatile(
        "{\n\t.reg .pred P;\n"
        "W%=:\n\t"
        "mbarrier.try_wait.parity.acquire.cta.shared::cta.b64 P, [%0], %1, 0x989680;\n\t"
        "@P bra D%=;\n\t"
        "bra W%=;\n"
        "D%=:\n\t}"
        :: "r"(m), "r"(parity) : "memory");
}
__device__ __forceinline__ void bulk_row(uint32_t mbar, uint32_t dst,
                                         const float* src) {
    asm volatile("mbarrier.arrive.expect_tx.shared.b64 _, [%0], %1;"
                 :: "r"(mbar), "r"(256) : "memory");
    asm volatile(
        "cp.async.bulk.shared::cluster.global.mbarrier::complete_tx::bytes "
        "[%0], [%1], 256, [%2];"
        :: "r"(dst), "l"(src), "r"(mbar) : "memory");
}

__global__ void __launch_bounds__(NT, 2)
attn_tf32_kernel(const float* __restrict__ Qg_, const float* __restrict__ Kg_,
                 const float* __restrict__ Vg_, const int* __restrict__ Mg_,
                 float* __restrict__ out)
{
    extern __shared__ float sm[];
    float* sS  = sm + 16;                 // [TQ][SS_P]
    float* sQ  = sS + TQ * SS_P;          // [TQ][SQ_P]; reused as reduction buf
    float* sKV = sQ + TQ * SQ_P;          // [4][BUF]

    const uint32_t mb  = s2u(sm);         // full[b]=mb+8b, empty[b]=mb+32+8b
    const uint32_t kvu = s2u(sKV);

    const int qt = blockIdx.x, bh = blockIdx.y, b = bh >> 4;
    const int tid = threadIdx.x, warp = tid >> 5, lane = tid & 31;
    const int gid = lane >> 2, tig = lane & 3;
    const int group = warp >> 2;          // 0: warps 0-3, 1: warps 4-7
    const int wg    = warp & 3;           // warp-in-group
    const bool prod = (warp == 0) || (warp == 4);   // per-group producer warp

    const float* Qg = Qg_ + ((size_t)bh * Sc + (size_t)qt * TQ) * Dc;
    const float* Kg = Kg_ + (size_t)bh * Sc * Dc;
    const float* Vg = Vg_ + (size_t)bh * Sc * Dc;
    float* outO = out + ((size_t)bh * Sc + (size_t)qt * TQ) * Dc;
    float* outA = out + ATTN_OFF + ((size_t)bh * Sc + (size_t)qt * TQ) * Sc;
    const int* Mg = Mg_ + ((size_t)b * Sc + (size_t)qt * TQ) * Sc;

    if (tid == 0) {
#pragma unroll
        for (int i = 0; i < 4; i++) {
            mbar_init(mb + i * 8, 32);          // full: 32 producer arrivals
            mbar_init(mb + 32 + i * 8, 128);    // empty: one group's threads
        }
    }
    {   // Q tile -> smem, *1/8, tf32
        int row = tid >> 4, c4 = tid & 15;
        float4 v = reinterpret_cast<const float4*>(Qg)[tid];
        float* dst = sQ + row * SQ_P + c4 * 4;
        dst[0] = to_tf32(v.x * 0.125f); dst[1] = to_tf32(v.y * 0.125f);
        dst[2] = to_tf32(v.z * 0.125f); dst[3] = to_tf32(v.w * 0.125f);
    }
    __syncthreads();

    // stage s: 0..31 = K tile s, 32..63 = V tile s-32; buffer = s&3
    auto issue = [&](int s) {
        int bsel = s & 3;
        uint32_t fb  = mb + bsel * 8;
        uint32_t dst = kvu + (uint32_t)bsel * (BUF * 4);
        if (s < 32)
            bulk_row(fb, dst + lane * (KP * 4),
                     Kg + ((size_t)s * KT + lane) * Dc);
        else
            bulk_row(fb, dst + lane * (VP * 4),
                     Vg + ((size_t)(s - 32) * KT + lane) * Dc);
    };
    if (warp == 0) { issue(0); issue(2); }
    if (warp == 4) { issue(1); issue(3); }

    // A fragments (Q): all warps need all 8 k-steps
    float aq[8][4];
#pragma unroll
    for (int ks = 0; ks < 8; ks++) {
        const float* p = sQ + gid * SQ_P + ks * 8 + tig;
        aq[ks][0] = p[0];   aq[ks][1] = p[8 * SQ_P];
        aq[ks][2] = p[4];   aq[ks][3] = p[8 * SQ_P + 4];
    }

    // ---------------- GEMM1: group g consumes K stages g, g+2, ... ----------
    {
        int s = group;
        for (int i = 0; i < 16; i++, s += 2) {
            int bsel = s & 3;
            mbar_wait(mb + bsel * 8, (s >> 2) & 1);          // full
            const float* kb = sKV + bsel * BUF;

            float cA[4] = {0,0,0,0}, cB[4] = {0,0,0,0};
#pragma unroll
            for (int ks = 0; ks < 8; ks += 2) {
                const float* bp0 = kb + (wg * 8 + gid) * KP + ks * 8 + tig;
                mma8(cA, aq[ks][0], aq[ks][1], aq[ks][2], aq[ks][3],
                     to_tf32(bp0[0]), to_tf32(bp0[4]));
                const float* bp1 = bp0 + 8;
                mma8(cB, aq[ks+1][0], aq[ks+1][1], aq[ks+1][2], aq[ks+1][3],
                     to_tf32(bp1[0]), to_tf32(bp1[4]));
            }
            int col = s * KT + wg * 8 + tig * 2;
            float* p  = sS + gid * SS_P + col;
            float* p2 = p + 8 * SS_P;
            p[0]  = cA[0] + cB[0]; p[1]  = cA[1] + cB[1];
            p2[0] = cA[2] + cB[2]; p2[1] = cA[3] + cB[3];

            mbar_arrive(mb + 32 + bsel * 8);                 // empty
            if (prod) {
                mbar_wait(mb + 32 + bsel * 8, (s >> 2) & 1);
                issue(s + 4);                                // s+4 <= 35
            }
        }
    }
    __syncthreads();

    // ---------------- softmax + post-softmax mask + attn write --------------
#pragma unroll
    for (int rr = 0; rr < 2; rr++) {
        int row = warp * 2 + rr;
        float4* srow4 = reinterpret_cast<float4*>(sS + row * SS_P);

        float mx = -3.0e38f;
#pragma unroll
        for (int i = 0; i < 8; i++) {
            float4 v = srow4[lane + i * 32];
            mx = fmaxf(mx, fmaxf(fmaxf(v.x, v.y), fmaxf(v.z, v.w)));
        }
#pragma unroll
        for (int o = 16; o > 0; o >>= 1)
            mx = fmaxf(mx, __shfl_xor_sync(0xffffffffu, mx, o));

        float sum = 0.f;
        float4 e[8];
#pragma unroll
        for (int i = 0; i < 8; i++) {
            float4 v = srow4[lane + i * 32];
            v.x = __expf(v.x - mx); v.y = __expf(v.y - mx);
            v.z = __expf(v.z - mx); v.w = __expf(v.w - mx);
            e[i] = v;
            sum += (v.x + v.y) + (v.z + v.w);
        }
#pragma unroll
        for (int o = 16; o > 0; o >>= 1)
            sum += __shfl_xor_sync(0xffffffffu, sum, o);
        float inv = 1.0f / sum;

        const int4* mrow = reinterpret_cast<const int4*>(Mg + (size_t)row * Sc);
        float4* arow = reinterpret_cast<float4*>(outA + (size_t)row * Sc);
#pragma unroll
        for (int i = 0; i < 8; i++) {
            int idx = lane + i * 32;
            int4 m = mrow[idx];
            float4 w;
            w.x = m.x ? e[i].x * inv : -100000.0f;
            w.y = m.y ? e[i].y * inv : -100000.0f;
            w.z = m.z ? e[i].z * inv : -100000.0f;
            w.w = m.w ? e[i].w * inv : -100000.0f;
            __stcs(&arow[idx], w);
            float4 t;
            t.x = to_tf32(w.x); t.y = to_tf32(w.y);
            t.z = to_tf32(w.z); t.w = to_tf32(w.w);
            srow4[idx] = t;
        }
    }
    __syncthreads();

    // ---------------- GEMM2: group g consumes V stages 32+g, 34+g, ... -------
    float c2[2][4] = {{0,0,0,0},{0,0,0,0}};
    {
        int s = 32 + group;
        for (int i = 0; i < 16; i++, s += 2) {
            int bsel = s & 3;
            mbar_wait(mb + bsel * 8, (s >> 2) & 1);          // full
            const float* vb = sKV + bsel * BUF;

#pragma unroll
            for (int ks = 0; ks < 4; ks++) {
                const float* ap = sS + gid * SS_P + (s - 32) * KT + ks * 8 + tig;
                float a0 = ap[0],  a1 = ap[8 * SS_P];
                float a2 = ap[4],  a3 = ap[8 * SS_P + 4];
#pragma unroll
                for (int nb = 0; nb < 2; nb++) {
                    const float* bp = vb + (ks * 8 + tig) * VP
                                      + wg * 16 + nb * 8 + gid;
                    mma8(c2[nb], a0, a1, a2, a3,
                         to_tf32(bp[0]), to_tf32(bp[4 * VP]));
                }
            }
            mbar_arrive(mb + 32 + bsel * 8);                 // empty
            if (prod && (s + 4) < 64) {
                mbar_wait(mb + 32 + bsel * 8, (s >> 2) & 1);
                issue(s + 4);
            }
        }
    }
    __syncthreads();

    // ---------------- combine the two groups' partials (reuse sQ) ------------
    float* sR = sQ;
    if (group == 1) {
#pragma unroll
        for (int nb = 0; nb < 2; nb++) {
            int dcol = wg * 16 + nb * 8 + tig * 2;
            *reinterpret_cast<float2*>(sR + gid * SQ_P + dcol) =
                make_float2(c2[nb][0], c2[nb][1]);
            *reinterpret_cast<float2*>(sR + (gid + 8) * SQ_P + dcol) =
                make_float2(c2[nb][2], c2[nb][3]);
        }
    }
    __syncthreads();
    if (group == 0) {
#pragma unroll
        for (int nb = 0; nb < 2; nb++) {
            int dcol = wg * 16 + nb * 8 + tig * 2;
            float2 o0 = *reinterpret_cast<const float2*>(sR + gid * SQ_P + dcol);
            float2 o1 = *reinterpret_cast<const float2*>(sR + (gid + 8) * SQ_P + dcol);
            *reinterpret_cast<float2*>(outO + gid * Dc + dcol) =
                make_float2(c2[nb][0] + o0.x, c2[nb][1] + o0.y);
            *reinterpret_cast<float2*>(outO + (gid + 8) * Dc + dcol) =
                make_float2(c2[nb][2] + o1.x, c2[nb][3] + o1.y);
        }
    }
}

extern "C" void kernel_launch(void* const* d_in, const int* in_sizes, int n_in,
                              void* d_out, int out_size)
{
    (void)in_sizes; (void)n_in; (void)out_size;
    const float* Q = (const float*)d_in[0];
    const float* K = (const float*)d_in[1];
    const float* V = (const float*)d_in[2];
    const int*   M = (const int*)d_in[3];
    float* out = (float*)d_out;

    cudaFuncSetAttribute(attn_tf32_kernel,
                         cudaFuncAttributeMaxDynamicSharedMemorySize,
                         SMEM_FLOATS * (int)sizeof(float));
    dim3 grid(Sc / TQ, BH);
    attn_tf32_kernel<<<grid, NT, SMEM_FLOATS * sizeof(float)>>>(Q, K, V, M, out);
}

// round 7
// speedup vs baseline: 2.2510x; 2.2510x over previous
#include <cuda_runtime.h>
#include <cstdint>

namespace {
constexpr int Bc = 8, Sc = 1024, Dc = 64, BH = 128;
constexpr int TQ = 16, NT = 256;
constexpr int SQ_P = 68;
constexpr int SS_P = 1028;
constexpr int SMEM_FLOATS = TQ * SS_P + TQ * SQ_P;   // 17536 fl = 70144 B
constexpr size_t ATTN_OFF = (size_t)BH * Sc * Dc;
}

// Scratch: fragment-packed tf32 K and V, bit-packed mask.
__device__ float    KF[(size_t)BH * Sc * Dc];          // 33.5 MB
__device__ float    VF[(size_t)BH * Sc * Dc];          // 33.5 MB
__device__ unsigned MBITS[(size_t)Bc * Sc * (Sc / 32)]; // 1 MB

__device__ __forceinline__ float to_tf32(float x) {
    uint32_t u;
    asm("cvt.rna.tf32.f32 %0, %1;" : "=r"(u) : "f"(x));
    return __uint_as_float(u);
}

__device__ __forceinline__ void mma8(float c[4],
                                     float a0, float a1, float a2, float a3,
                                     float b0, float b1) {
    asm volatile(
        "mma.sync.aligned.m16n8k8.row.col.f32.tf32.tf32.f32 "
        "{%0,%1,%2,%3}, {%4,%5,%6,%7}, {%8,%9}, {%0,%1,%2,%3};\n"
        : "+f"(c[0]), "+f"(c[1]), "+f"(c[2]), "+f"(c[3])
        : "r"(__float_as_uint(a0)), "r"(__float_as_uint(a1)),
          "r"(__float_as_uint(a2)), "r"(__float_as_uint(a3)),
          "r"(__float_as_uint(b0)), "r"(__float_as_uint(b1)));
}

// ---- pack K: blocks of 8 n-rows x 8 d-cols; pair idx=g*4+t -> (K[g][t], K[g][t+4])
__global__ void pack_k_kernel(const float* __restrict__ K) {
    __shared__ float t[8][65];
    int blk = blockIdx.x;                  // bh*128 + sblk
    int i = threadIdx.x;                   // 0..127
    float4 v = reinterpret_cast<const float4*>(K + (size_t)blk * 512)[i];
    int row = i >> 4, c4 = (i & 15) * 4;
    t[row][c4 + 0] = to_tf32(v.x);  t[row][c4 + 1] = to_tf32(v.y);
    t[row][c4 + 2] = to_tf32(v.z);  t[row][c4 + 3] = to_tf32(v.w);
    __syncthreads();
    float* dst = KF + (size_t)blk * 512;
#pragma unroll
    for (int j = 0; j < 2; j++) {
        int o = i + j * 128;               // 0..255
        int dblk = o >> 5, idx = o & 31, g = idx >> 2, tt = idx & 3;
        float2 p = make_float2(t[g][dblk * 8 + tt], t[g][dblk * 8 + tt + 4]);
        reinterpret_cast<float2*>(dst + dblk * 64)[idx] = p;
    }
}

// ---- pack V: blocks of 8 k-rows x 8 d-cols; pair idx=g*4+t -> (V[t][g], V[t+4][g])
__global__ void pack_v_kernel(const float* __restrict__ V) {
    __shared__ float t[8][65];
    int blk = blockIdx.x;                  // bh*128 + kblk
    int i = threadIdx.x;
    float4 v = reinterpret_cast<const float4*>(V + (size_t)blk * 512)[i];
    int row = i >> 4, c4 = (i & 15) * 4;
    t[row][c4 + 0] = to_tf32(v.x);  t[row][c4 + 1] = to_tf32(v.y);
    t[row][c4 + 2] = to_tf32(v.z);  t[row][c4 + 3] = to_tf32(v.w);
    __syncthreads();
    float* dst = VF + (size_t)blk * 512;
#pragma unroll
    for (int j = 0; j < 2; j++) {
        int o = i + j * 128;
        int dblk = o >> 5, idx = o & 31, g = idx >> 2, tt = idx & 3;
        float2 p = make_float2(t[tt][dblk * 8 + g], t[tt + 4][dblk * 8 + g]);
        reinterpret_cast<float2*>(dst + dblk * 64)[idx] = p;
    }
}

// ---- mask -> bits (1 word per 32 k-positions)
__global__ void mask_bits_kernel(const int* __restrict__ M) {
    size_t i = (size_t)blockIdx.x * 256 + threadIdx.x;
    unsigned bal = __ballot_sync(0xffffffffu, M[i] != 0);
    if ((threadIdx.x & 31) == 0) MBITS[i >> 5] = bal;
}

__global__ void __launch_bounds__(NT, 2)
attn_tf32_kernel(const float* __restrict__ Qg_, float* __restrict__ out)
{
    extern __shared__ float sm[];
    float* sS = sm;                       // [TQ][SS_P]
    float* sQ = sS + TQ * SS_P;           // [TQ][SQ_P]; reused as reduction buf

    const int qt = blockIdx.x, bh = blockIdx.y, b = bh >> 4;
    const int tid = threadIdx.x, warp = tid >> 5, lane = tid & 31;
    const int gid = lane >> 2, tig = lane & 3, w8 = warp << 3;

    const float* Qg = Qg_ + ((size_t)bh * Sc + (size_t)qt * TQ) * Dc;
    float* outO = out + ((size_t)bh * Sc + (size_t)qt * TQ) * Dc;
    float* outA = out + ATTN_OFF + ((size_t)bh * Sc + (size_t)qt * TQ) * Sc;

    {   // Q tile -> smem, *1/8, tf32
        int row = tid >> 4, c4 = tid & 15;
        float4 v = reinterpret_cast<const float4*>(Qg)[tid];
        float* dst = sQ + row * SQ_P + c4 * 4;
        dst[0] = to_tf32(v.x * 0.125f); dst[1] = to_tf32(v.y * 0.125f);
        dst[2] = to_tf32(v.z * 0.125f); dst[3] = to_tf32(v.w * 0.125f);
    }
    __syncthreads();

    // A fragments (Q), reused across all 16 K tiles
    float aq[8][4];
#pragma unroll
    for (int ks = 0; ks < 8; ks++) {
        const float* p = sQ + gid * SQ_P + ks * 8 + tig;
        aq[ks][0] = p[0];   aq[ks][1] = p[8 * SQ_P];
        aq[ks][2] = p[4];   aq[ks][3] = p[8 * SQ_P + 4];
    }

    // ---------------- GEMM1: B frags = 1 LDG.64/block from KF ---------------
    {
        // warp's block for tile kt: sblk = kt*8 + warp
        const float* kfw = KF + ((size_t)bh * 128 + warp) * 512 + lane * 2;
        float2 bf[2][8];
#pragma unroll
        for (int ks = 0; ks < 8; ks++)
            bf[0][ks] = *reinterpret_cast<const float2*>(kfw + ks * 64);

        for (int kt = 0; kt < 16; kt++) {
            int cur = kt & 1;
            if (kt < 15) {
                const float* nx = kfw + (size_t)(kt + 1) * 4096;
#pragma unroll
                for (int ks = 0; ks < 8; ks++)
                    bf[cur ^ 1][ks] = *reinterpret_cast<const float2*>(nx + ks * 64);
            }
            float cA[4] = {0,0,0,0}, cB[4] = {0,0,0,0};
#pragma unroll
            for (int ks = 0; ks < 8; ks += 2) {
                mma8(cA, aq[ks][0], aq[ks][1], aq[ks][2], aq[ks][3],
                     bf[cur][ks].x, bf[cur][ks].y);
                mma8(cB, aq[ks+1][0], aq[ks+1][1], aq[ks+1][2], aq[ks+1][3],
                     bf[cur][ks+1].x, bf[cur][ks+1].y);
            }
            int col = kt * 64 + w8 + tig * 2;
            float* p  = sS + gid * SS_P + col;
            float* p2 = p + 8 * SS_P;
            p[0]  = cA[0] + cB[0]; p[1]  = cA[1] + cB[1];
            p2[0] = cA[2] + cB[2]; p2[1] = cA[3] + cB[3];
        }
    }
    __syncthreads();

    // ---------------- softmax + bitmask + attn write (single read pass) ------
#pragma unroll
    for (int rr = 0; rr < 2; rr++) {
        int row = warp * 2 + rr;
        float4* srow4 = reinterpret_cast<float4*>(sS + row * SS_P);
        unsigned mw = MBITS[((size_t)(b * Sc + qt * TQ + row)) * 32 + lane];

        float4 v[8];
        float mx = -3.0e38f;
#pragma unroll
        for (int i = 0; i < 8; i++) {
            v[i] = srow4[lane + i * 32];
            mx = fmaxf(mx, fmaxf(fmaxf(v[i].x, v[i].y), fmaxf(v[i].z, v[i].w)));
        }
#pragma unroll
        for (int o = 16; o > 0; o >>= 1)
            mx = fmaxf(mx, __shfl_xor_sync(0xffffffffu, mx, o));

        float sum = 0.f;
#pragma unroll
        for (int i = 0; i < 8; i++) {
            v[i].x = __expf(v[i].x - mx); v[i].y = __expf(v[i].y - mx);
            v[i].z = __expf(v[i].z - mx); v[i].w = __expf(v[i].w - mx);
            sum += (v[i].x + v[i].y) + (v[i].z + v[i].w);
        }
#pragma unroll
        for (int o = 16; o > 0; o >>= 1)
            sum += __shfl_xor_sync(0xffffffffu, sum, o);
        float inv = 1.0f / sum;

        float4* arow = reinterpret_cast<float4*>(outA + (size_t)row * Sc);
#pragma unroll
        for (int i = 0; i < 8; i++) {
            int idx = lane + i * 32;
            unsigned wd  = __shfl_sync(0xffffffffu, mw, (lane >> 3) + 4 * i);
            unsigned nib = wd >> ((lane & 7) * 4);
            float4 w;
            w.x = (nib & 1u) ? v[i].x * inv : -100000.0f;
            w.y = (nib & 2u) ? v[i].y * inv : -100000.0f;
            w.z = (nib & 4u) ? v[i].z * inv : -100000.0f;
            w.w = (nib & 8u) ? v[i].w * inv : -100000.0f;
            __stcs(&arow[idx], w);
            float4 t;
            t.x = to_tf32(w.x); t.y = to_tf32(w.y);
            t.z = to_tf32(w.z); t.w = to_tf32(w.w);
            srow4[idx] = t;
        }
    }
    __syncthreads();

    // ---------------- GEMM2: hybrid split; B frags 1 LDG.64/block from VF ----
    // half h (warps 4h..4h+3) covers k-tiles h*8..h*8+7; warp covers 16 d-cols.
    const int half = warp >> 2, w4 = warp & 3;
    float c2[2][4] = {{0,0,0,0},{0,0,0,0}};
    {
        // chunk q = it*2 + c  (it: tile in half, c: ks half), 4 ks per chunk
        const float* vfb = VF + (size_t)bh * 65536
                           + (size_t)half * 8 * 4096 + lane * 2;
        float2 bv[2][4][2];
        auto ldchunk = [&](int q, float2 dst[4][2]) {
            int it_ = q >> 1, c_ = q & 1;
            const float* base = vfb + (size_t)it_ * 4096 + c_ * 4 * 512;
#pragma unroll
            for (int k4 = 0; k4 < 4; k4++)
#pragma unroll
                for (int nb = 0; nb < 2; nb++)
                    dst[k4][nb] = *reinterpret_cast<const float2*>(
                        base + k4 * 512 + (w4 * 2 + nb) * 64);
        };
        ldchunk(0, bv[0]);
        for (int q = 0; q < 16; q++) {
            int cur = q & 1;
            if (q < 15) ldchunk(q + 1, bv[cur ^ 1]);
            int it = q >> 1, c = q & 1;
            int vt = half * 8 + it;
#pragma unroll
            for (int k4 = 0; k4 < 4; k4++) {
                int ks = c * 4 + k4;
                const float* ap = sS + gid * SS_P + vt * 64 + ks * 8 + tig;
                float a0 = ap[0],  a1 = ap[8 * SS_P];
                float a2 = ap[4],  a3 = ap[8 * SS_P + 4];
#pragma unroll
                for (int nb = 0; nb < 2; nb++)
                    mma8(c2[nb], a0, a1, a2, a3,
                         bv[cur][k4][nb].x, bv[cur][k4][nb].y);
            }
        }
    }
    __syncthreads();      // all reads of sS attn done

    // ---------------- combine halves (reuse sQ as 16x68 buffer) --------------
    float* sR = sQ;
    if (half == 1) {
#pragma unroll
        for (int nb = 0; nb < 2; nb++) {
            int dcol = w4 * 16 + nb * 8 + tig * 2;
            *reinterpret_cast<float2*>(sR + gid * SQ_P + dcol) =
                make_float2(c2[nb][0], c2[nb][1]);
            *reinterpret_cast<float2*>(sR + (gid + 8) * SQ_P + dcol) =
                make_float2(c2[nb][2], c2[nb][3]);
        }
    }
    __syncthreads();
    if (half == 0) {
#pragma unroll
        for (int nb = 0; nb < 2; nb++) {
            int dcol = w4 * 16 + nb * 8 + tig * 2;
            float2 o0 = *reinterpret_cast<const float2*>(sR + gid * SQ_P + dcol);
            float2 o1 = *reinterpret_cast<const float2*>(sR + (gid + 8) * SQ_P + dcol);
            *reinterpret_cast<float2*>(outO + gid * Dc + dcol) =
                make_float2(c2[nb][0] + o0.x, c2[nb][1] + o0.y);
            *reinterpret_cast<float2*>(outO + (gid + 8) * Dc + dcol) =
                make_float2(c2[nb][2] + o1.x, c2[nb][3] + o1.y);
        }
    }
}

extern "C" void kernel_launch(void* const* d_in, const int* in_sizes, int n_in,
                              void* d_out, int out_size)
{
    (void)in_sizes; (void)n_in; (void)out_size;
    const float* Q = (const float*)d_in[0];
    const float* K = (const float*)d_in[1];
    const float* V = (const float*)d_in[2];
    const int*   M = (const int*)d_in[3];
    float* out = (float*)d_out;

    pack_k_kernel<<<BH * 128, 128>>>(K);
    pack_v_kernel<<<BH * 128, 128>>>(V);
    mask_bits_kernel<<<(Bc * Sc * Sc) / 256, 256>>>(M);

    cudaFuncSetAttribute(attn_tf32_kernel,
                         cudaFuncAttributeMaxDynamicSharedMemorySize,
                         SMEM_FLOATS * (int)sizeof(float));
    dim3 grid(Sc / TQ, BH);
    attn_tf32_kernel<<<grid, NT, SMEM_FLOATS * sizeof(float)>>>(Q, out);
}